// round 15
// baseline (speedup 1.0000x reference)
#include <cuda_runtime.h>
#include <cstdint>

#define Hh 512
#define Ww 512
#define Cc 32
#define Bb 4
#define Ss (Hh*Ww)
#define NG 4               // conv channel groups
#define CPG (Cc/NG)        // 8 channels per group

// Partial per-pixel (off_x, off_y) per channel-group: 4 * 8MB = 32 MB scratch
__device__ float2 g_off_part[NG][Bb * Ss];

typedef unsigned long long ull;

__device__ __forceinline__ ull pack2(float a, float b) {
    ull r; asm("mov.b64 %0, {%1, %2};" : "=l"(r) : "f"(a), "f"(b)); return r;
}
__device__ __forceinline__ void unpack2(ull v, float& a, float& b) {
    asm("mov.b64 {%0, %1}, %2;" : "=f"(a), "=f"(b) : "l"(v));
}
__device__ __forceinline__ ull fma2(ull a, ull b, ull c) {
    ull d; asm("fma.rn.f32x2 %0, %1, %2, %3;" : "=l"(d) : "l"(a), "l"(b), "l"(c)); return d;
}

// ---------------------------------------------------------------------------
// Kernel 1: channel-split conv with 2-channel ILP interleave (R13 — measured
// 34.7us full-batch; DRAM 54.6% / fma 45.3%, at its traffic floor). R15: one
// BATCH per launch (grid.z = NG) so each batch's sampler can start as soon as
// its conv finishes, overlapping the remaining convs on another stream.
// ---------------------------------------------------------------------------
__global__ __launch_bounds__(64) void conv_off_kernel(
    const float* __restrict__ x,
    const float* __restrict__ w_off,
    const float* __restrict__ b_off,
    int bz)
{
    __shared__ ull s_wk[CPG * 9];

    const int tid  = threadIdx.x;
    const int wid  = tid >> 5;
    const int lane = tid & 31;

    const int grp = blockIdx.z;
    const int c0  = grp * CPG;

    for (int i = tid; i < CPG * 9; i += 64)
        s_wk[i] = pack2(__ldg(w_off + c0 * 9 + i),
                        __ldg(w_off + 288 + c0 * 9 + i));
    __syncthreads();

    const int X0   = blockIdx.x * 128;
    const int ytop = blockIdx.y * 8 + wid * 4;
    const int cb   = X0 + 4 * lane;
    const float* xb = x + (size_t)bz * Cc * Ss;

    const ull initp = (grp == 0) ? pack2(__ldg(b_off + 0), __ldg(b_off + 1))
                                 : pack2(0.0f, 0.0f);
    ull acc[4][4];
#pragma unroll
    for (int r = 0; r < 4; r++)
#pragma unroll
        for (int p = 0; p < 4; p++) acc[r][p] = initp;

    const bool has_left  = (cb > 0);
    const bool has_right = (cb + 4 < Ww);

#pragma unroll
    for (int c = 0; c < CPG; c += 2) {
        const float* xcA = xb + (size_t)(c0 + c) * Ss;
        const float* xcB = xcA + Ss;

        ull wkA[9], wkB[9];
#pragma unroll
        for (int k = 0; k < 9; k++) {
            wkA[k] = s_wk[c * 9 + k];
            wkB[k] = s_wk[(c + 1) * 9 + k];
        }

        float4 mA[6], mB[6];
        float  lA[6], rA[6], lB[6], rB[6];
#pragma unroll
        for (int j = 0; j < 6; j++) {
            int gy = ytop - 1 + j;
            mA[j] = make_float4(0.f, 0.f, 0.f, 0.f);
            mB[j] = make_float4(0.f, 0.f, 0.f, 0.f);
            lA[j] = rA[j] = lB[j] = rB[j] = 0.f;
            if ((unsigned)gy < (unsigned)Hh) {
                const float* rpA = xcA + gy * Ww + cb;
                const float* rpB = xcB + gy * Ww + cb;
                mA[j] = __ldg(reinterpret_cast<const float4*>(rpA));
                mB[j] = __ldg(reinterpret_cast<const float4*>(rpB));
                if (has_left)  { lA[j] = __ldg(rpA - 1); lB[j] = __ldg(rpB - 1); }
                if (has_right) { rA[j] = __ldg(rpA + 4); rB[j] = __ldg(rpB + 4); }
            }
        }

#pragma unroll
        for (int j = 0; j < 6; j++) {
            ull pvA[6], pvB[6];
            pvA[0] = pack2(lA[j], lA[j]);     pvB[0] = pack2(lB[j], lB[j]);
            pvA[1] = pack2(mA[j].x, mA[j].x); pvB[1] = pack2(mB[j].x, mB[j].x);
            pvA[2] = pack2(mA[j].y, mA[j].y); pvB[2] = pack2(mB[j].y, mB[j].y);
            pvA[3] = pack2(mA[j].z, mA[j].z); pvB[3] = pack2(mB[j].z, mB[j].z);
            pvA[4] = pack2(mA[j].w, mA[j].w); pvB[4] = pack2(mB[j].w, mB[j].w);
            pvA[5] = pack2(rA[j], rA[j]);     pvB[5] = pack2(rB[j], rB[j]);

#pragma unroll
            for (int ky = 0; ky < 3; ky++) {
                int r = j - ky;
                if (r >= 0 && r < 4) {
#pragma unroll
                    for (int p = 0; p < 4; p++) {
                        ull a = acc[r][p];
                        a = fma2(pvA[p],     wkA[ky * 3 + 0], a);
                        a = fma2(pvA[p + 1], wkA[ky * 3 + 1], a);
                        a = fma2(pvA[p + 2], wkA[ky * 3 + 2], a);
                        a = fma2(pvB[p],     wkB[ky * 3 + 0], a);
                        a = fma2(pvB[p + 1], wkB[ky * 3 + 1], a);
                        a = fma2(pvB[p + 2], wkB[ky * 3 + 2], a);
                        acc[r][p] = a;
                    }
                }
            }
        }
    }

#pragma unroll
    for (int r = 0; r < 4; r++) {
        int y = ytop + r;
        float2* op = g_off_part[grp] + (size_t)bz * Ss + (size_t)y * Ww + cb;
        float ox0, oy0, ox1, oy1, ox2, oy2, ox3, oy3;
        unpack2(acc[r][0], ox0, oy0);
        unpack2(acc[r][1], ox1, oy1);
        unpack2(acc[r][2], ox2, oy2);
        unpack2(acc[r][3], ox3, oy3);
        *reinterpret_cast<float4*>(op)     = make_float4(ox0, oy0, ox1, oy1);
        *reinterpret_cast<float4*>(op + 2) = make_float4(ox2, oy2, ox3, oy3);
    }
}

// ---------------------------------------------------------------------------
// Kernel 2: direct-gather bilinear sampler, R13-exact (proven 66.5us; R14
// showed it saturates L1 wavefront throughput — widening lost). One batch per
// launch. Sums the 4 conv partials, full clamp+validity (jnp semantics),
// coalesced channel loop + streaming stores.
// ---------------------------------------------------------------------------
__global__ __launch_bounds__(256) void sample_kernel(
    const float* __restrict__ x,
    float* __restrict__ out,
    int b)
{
    const int px = blockIdx.x * 64 + threadIdx.x;
    const int py = blockIdx.y * 4 + threadIdx.y;

    const size_t oidx = (size_t)b * Ss + (size_t)py * Ww + px;
    float2 p0 = __ldg(&g_off_part[0][oidx]);
    float2 p1 = __ldg(&g_off_part[1][oidx]);
    float2 p2 = __ldg(&g_off_part[2][oidx]);
    float2 p3 = __ldg(&g_off_part[3][oidx]);
    float offx = (p0.x + p1.x) + (p2.x + p3.x);
    float offy = (p0.y + p1.y) + (p2.y + p3.y);

    float ix = (float)px + offx;
    float iy = (float)py + offy;

    float x0f = floorf(ix);
    float y0f = floorf(iy);
    float wx1 = ix - x0f, wx0 = 1.0f - wx1;
    float wy1 = iy - y0f, wy0 = 1.0f - wy1;

    float fx0 = (x0f >= 0.0f && x0f <= 511.0f) ? 1.0f : 0.0f;
    float fx1 = (x0f >= -1.0f && x0f <= 510.0f) ? 1.0f : 0.0f;
    float fy0 = (y0f >= 0.0f && y0f <= 511.0f) ? 1.0f : 0.0f;
    float fy1 = (y0f >= -1.0f && y0f <= 510.0f) ? 1.0f : 0.0f;

    int ix0r = (int)x0f;
    int iy0r = (int)y0f;
    int xi0 = max(0, min(511, ix0r));
    int xi1 = max(0, min(511, ix0r + 1));
    int yi0 = max(0, min(511, iy0r));
    int yi1 = max(0, min(511, iy0r + 1));

    float w00 = wy0 * wx0 * (fy0 * fx0);
    float w01 = wy0 * wx1 * (fy0 * fx1);
    float w10 = wy1 * wx0 * (fy1 * fx0);
    float w11 = wy1 * wx1 * (fy1 * fx1);

    const int i00 = yi0 * Ww + xi0;
    const int i01 = yi0 * Ww + xi1;
    const int i10 = yi1 * Ww + xi0;
    const int i11 = yi1 * Ww + xi1;

    const float* xb = x + (size_t)b * Cc * Ss;
    size_t o = (size_t)b * Cc * Ss + (size_t)py * Ww + px;

#pragma unroll 4
    for (int c = 0; c < Cc; c++) {
        const float* p = xb + (size_t)c * Ss;
        float v = w00 * __ldg(p + i00)
                + w01 * __ldg(p + i01)
                + w10 * __ldg(p + i10)
                + w11 * __ldg(p + i11);
        __stcs(out + o + (size_t)c * Ss, v);
    }
}

extern "C" void kernel_launch(void* const* d_in, const int* in_sizes, int n_in,
                              void* d_out, int out_size)
{
    const float* x     = (const float*)d_in[0];  // (4, 32, 512, 512)
    const float* w_off = (const float*)d_in[1];  // (18, 32, 3, 3)
    const float* b_off = (const float*)d_in[2];  // (18,)
    float* out = (float*)d_out;                  // (4, 32, 512, 512)

    (void)in_sizes; (void)n_in; (void)out_size;

    // One-time host-side resources (no device memory). Behavior is identical
    // on every call: same launches, same dependencies.
    static cudaStream_t s2 = nullptr;
    static cudaEvent_t evb[Bb];
    static cudaEvent_t fin;
    if (s2 == nullptr) {
        cudaStreamCreateWithFlags(&s2, cudaStreamNonBlocking);
        for (int b = 0; b < Bb; b++)
            cudaEventCreateWithFlags(&evb[b], cudaEventDisableTiming);
        cudaEventCreateWithFlags(&fin, cudaEventDisableTiming);
    }

    dim3 gc(Ww / 128, Hh / 8, NG);   // (4, 64, 4) blocks x 64 thr, per batch
    dim3 gs(Ww / 64, Hh / 4, 1);     // (8, 128) blocks, per batch
    dim3 ts(64, 4);

    // Pipeline: convs stream down s0 (DRAM-heavy); each batch's sampler
    // (L1-heavy) starts on s2 as soon as that batch's conv finishes —
    // complementary pipes overlap. Fork/join via events (graph edges).
    for (int b = 0; b < Bb; b++) {
        conv_off_kernel<<<gc, 64>>>(x, w_off, b_off, b);
        cudaEventRecord(evb[b], 0);
    }
    for (int b = 0; b < Bb; b++) {
        cudaStreamWaitEvent(s2, evb[b], 0);
        sample_kernel<<<gs, ts, 0, s2>>>(x, out, b);
    }
    cudaEventRecord(fin, s2);
    cudaStreamWaitEvent(0, fin, 0);
}

// round 16
// speedup vs baseline: 1.0212x; 1.0212x over previous
#include <cuda_runtime.h>
#include <cstdint>

#define Hh 512
#define Ww 512
#define Cc 32
#define Bb 4
#define Ss (Hh*Ww)
#define NG 4               // conv channel groups
#define CPG (Cc/NG)        // 8 channels per group

// Partial per-pixel (off_x, off_y) per channel-group: 4 * 8MB = 32 MB scratch
__device__ float2 g_off_part[NG][Bb * Ss];

typedef unsigned long long ull;

__device__ __forceinline__ ull pack2(float a, float b) {
    ull r; asm("mov.b64 %0, {%1, %2};" : "=l"(r) : "f"(a), "f"(b)); return r;
}
__device__ __forceinline__ void unpack2(ull v, float& a, float& b) {
    asm("mov.b64 {%0, %1}, %2;" : "=f"(a), "=f"(b) : "l"(v));
}
__device__ __forceinline__ ull fma2(ull a, ull b, ull c) {
    ull d; asm("fma.rn.f32x2 %0, %1, %2, %3;" : "=l"(d) : "l"(a), "l"(b), "l"(c)); return d;
}

// ---------------------------------------------------------------------------
// Kernel 1: channel-split conv with 2-channel ILP interleave (R13 math).
// R16: TWO batches per launch (grid.z = 2*NG = 8 -> 2048 blocks), the largest
// split that still pipelines with the sampler. R15 evidence: 1024-block
// launches dropped conv BW to 2.4TB/s; 4096 blocks reach 4.3TB/s; 2048 should
// sit near ~3.8TB/s while enabling convB to hide under sampA.
// ---------------------------------------------------------------------------
__global__ __launch_bounds__(64) void conv_off_kernel(
    const float* __restrict__ x,
    const float* __restrict__ w_off,
    const float* __restrict__ b_off,
    int b0)
{
    __shared__ ull s_wk[CPG * 9];

    const int tid  = threadIdx.x;
    const int wid  = tid >> 5;
    const int lane = tid & 31;

    const int grp = blockIdx.z & (NG - 1);
    const int bz  = b0 + (blockIdx.z >> 2);
    const int c0  = grp * CPG;

    for (int i = tid; i < CPG * 9; i += 64)
        s_wk[i] = pack2(__ldg(w_off + c0 * 9 + i),
                        __ldg(w_off + 288 + c0 * 9 + i));
    __syncthreads();

    const int X0   = blockIdx.x * 128;
    const int ytop = blockIdx.y * 8 + wid * 4;
    const int cb   = X0 + 4 * lane;
    const float* xb = x + (size_t)bz * Cc * Ss;

    const ull initp = (grp == 0) ? pack2(__ldg(b_off + 0), __ldg(b_off + 1))
                                 : pack2(0.0f, 0.0f);
    ull acc[4][4];
#pragma unroll
    for (int r = 0; r < 4; r++)
#pragma unroll
        for (int p = 0; p < 4; p++) acc[r][p] = initp;

    const bool has_left  = (cb > 0);
    const bool has_right = (cb + 4 < Ww);

#pragma unroll
    for (int c = 0; c < CPG; c += 2) {
        const float* xcA = xb + (size_t)(c0 + c) * Ss;
        const float* xcB = xcA + Ss;

        ull wkA[9], wkB[9];
#pragma unroll
        for (int k = 0; k < 9; k++) {
            wkA[k] = s_wk[c * 9 + k];
            wkB[k] = s_wk[(c + 1) * 9 + k];
        }

        float4 mA[6], mB[6];
        float  lA[6], rA[6], lB[6], rB[6];
#pragma unroll
        for (int j = 0; j < 6; j++) {
            int gy = ytop - 1 + j;
            mA[j] = make_float4(0.f, 0.f, 0.f, 0.f);
            mB[j] = make_float4(0.f, 0.f, 0.f, 0.f);
            lA[j] = rA[j] = lB[j] = rB[j] = 0.f;
            if ((unsigned)gy < (unsigned)Hh) {
                const float* rpA = xcA + gy * Ww + cb;
                const float* rpB = xcB + gy * Ww + cb;
                mA[j] = __ldg(reinterpret_cast<const float4*>(rpA));
                mB[j] = __ldg(reinterpret_cast<const float4*>(rpB));
                if (has_left)  { lA[j] = __ldg(rpA - 1); lB[j] = __ldg(rpB - 1); }
                if (has_right) { rA[j] = __ldg(rpA + 4); rB[j] = __ldg(rpB + 4); }
            }
        }

#pragma unroll
        for (int j = 0; j < 6; j++) {
            ull pvA[6], pvB[6];
            pvA[0] = pack2(lA[j], lA[j]);     pvB[0] = pack2(lB[j], lB[j]);
            pvA[1] = pack2(mA[j].x, mA[j].x); pvB[1] = pack2(mB[j].x, mB[j].x);
            pvA[2] = pack2(mA[j].y, mA[j].y); pvB[2] = pack2(mB[j].y, mB[j].y);
            pvA[3] = pack2(mA[j].z, mA[j].z); pvB[3] = pack2(mB[j].z, mB[j].z);
            pvA[4] = pack2(mA[j].w, mA[j].w); pvB[4] = pack2(mB[j].w, mB[j].w);
            pvA[5] = pack2(rA[j], rA[j]);     pvB[5] = pack2(rB[j], rB[j]);

#pragma unroll
            for (int ky = 0; ky < 3; ky++) {
                int r = j - ky;
                if (r >= 0 && r < 4) {
#pragma unroll
                    for (int p = 0; p < 4; p++) {
                        ull a = acc[r][p];
                        a = fma2(pvA[p],     wkA[ky * 3 + 0], a);
                        a = fma2(pvA[p + 1], wkA[ky * 3 + 1], a);
                        a = fma2(pvA[p + 2], wkA[ky * 3 + 2], a);
                        a = fma2(pvB[p],     wkB[ky * 3 + 0], a);
                        a = fma2(pvB[p + 1], wkB[ky * 3 + 1], a);
                        a = fma2(pvB[p + 2], wkB[ky * 3 + 2], a);
                        acc[r][p] = a;
                    }
                }
            }
        }
    }

#pragma unroll
    for (int r = 0; r < 4; r++) {
        int y = ytop + r;
        float2* op = g_off_part[grp] + (size_t)bz * Ss + (size_t)y * Ww + cb;
        float ox0, oy0, ox1, oy1, ox2, oy2, ox3, oy3;
        unpack2(acc[r][0], ox0, oy0);
        unpack2(acc[r][1], ox1, oy1);
        unpack2(acc[r][2], ox2, oy2);
        unpack2(acc[r][3], ox3, oy3);
        *reinterpret_cast<float4*>(op)     = make_float4(ox0, oy0, ox1, oy1);
        *reinterpret_cast<float4*>(op + 2) = make_float4(ox2, oy2, ox3, oy3);
    }
}

// ---------------------------------------------------------------------------
// Kernel 2: direct-gather bilinear sampler (R13-exact math, proven at its L1
// wavefront floor). TWO batches per launch (grid.z = 2). Sums the 4 conv
// partials, full clamp+validity (jnp semantics), streaming stores.
// ---------------------------------------------------------------------------
__global__ __launch_bounds__(256) void sample_kernel(
    const float* __restrict__ x,
    float* __restrict__ out,
    int b0)
{
    const int px = blockIdx.x * 64 + threadIdx.x;
    const int py = blockIdx.y * 4 + threadIdx.y;
    const int b  = b0 + blockIdx.z;

    const size_t oidx = (size_t)b * Ss + (size_t)py * Ww + px;
    float2 p0 = __ldg(&g_off_part[0][oidx]);
    float2 p1 = __ldg(&g_off_part[1][oidx]);
    float2 p2 = __ldg(&g_off_part[2][oidx]);
    float2 p3 = __ldg(&g_off_part[3][oidx]);
    float offx = (p0.x + p1.x) + (p2.x + p3.x);
    float offy = (p0.y + p1.y) + (p2.y + p3.y);

    float ix = (float)px + offx;
    float iy = (float)py + offy;

    float x0f = floorf(ix);
    float y0f = floorf(iy);
    float wx1 = ix - x0f, wx0 = 1.0f - wx1;
    float wy1 = iy - y0f, wy0 = 1.0f - wy1;

    float fx0 = (x0f >= 0.0f && x0f <= 511.0f) ? 1.0f : 0.0f;
    float fx1 = (x0f >= -1.0f && x0f <= 510.0f) ? 1.0f : 0.0f;
    float fy0 = (y0f >= 0.0f && y0f <= 511.0f) ? 1.0f : 0.0f;
    float fy1 = (y0f >= -1.0f && y0f <= 510.0f) ? 1.0f : 0.0f;

    int ix0r = (int)x0f;
    int iy0r = (int)y0f;
    int xi0 = max(0, min(511, ix0r));
    int xi1 = max(0, min(511, ix0r + 1));
    int yi0 = max(0, min(511, iy0r));
    int yi1 = max(0, min(511, iy0r + 1));

    float w00 = wy0 * wx0 * (fy0 * fx0);
    float w01 = wy0 * wx1 * (fy0 * fx1);
    float w10 = wy1 * wx0 * (fy1 * fx0);
    float w11 = wy1 * wx1 * (fy1 * fx1);

    const int i00 = yi0 * Ww + xi0;
    const int i01 = yi0 * Ww + xi1;
    const int i10 = yi1 * Ww + xi0;
    const int i11 = yi1 * Ww + xi1;

    const float* xb = x + (size_t)b * Cc * Ss;
    size_t o = (size_t)b * Cc * Ss + (size_t)py * Ww + px;

#pragma unroll 4
    for (int c = 0; c < Cc; c++) {
        const float* p = xb + (size_t)c * Ss;
        float v = w00 * __ldg(p + i00)
                + w01 * __ldg(p + i01)
                + w10 * __ldg(p + i10)
                + w11 * __ldg(p + i11);
        __stcs(out + o + (size_t)c * Ss, v);
    }
}

extern "C" void kernel_launch(void* const* d_in, const int* in_sizes, int n_in,
                              void* d_out, int out_size)
{
    const float* x     = (const float*)d_in[0];  // (4, 32, 512, 512)
    const float* w_off = (const float*)d_in[1];  // (18, 32, 3, 3)
    const float* b_off = (const float*)d_in[2];  // (18,)
    float* out = (float*)d_out;                  // (4, 32, 512, 512)

    (void)in_sizes; (void)n_in; (void)out_size;

    // One-time host-side resources (no device memory); identical behavior
    // every call.
    static cudaStream_t s2 = nullptr;
    static cudaEvent_t evA, evB, fin;
    if (s2 == nullptr) {
        cudaStreamCreateWithFlags(&s2, cudaStreamNonBlocking);
        cudaEventCreateWithFlags(&evA, cudaEventDisableTiming);
        cudaEventCreateWithFlags(&evB, cudaEventDisableTiming);
        cudaEventCreateWithFlags(&fin, cudaEventDisableTiming);
    }

    dim3 gc(Ww / 128, Hh / 8, 2 * NG);   // 2048 blocks x 64 thr (2 batches)
    dim3 gs(Ww / 64, Hh / 4, 2);         // 2048 blocks (2 batches)
    dim3 ts(64, 4);

    // Half-granularity pipeline: convB (DRAM pipe) hides under sampA
    // (L1 pipe). Fork/join via events -> graph edges.
    conv_off_kernel<<<gc, 64>>>(x, w_off, b_off, 0);
    cudaEventRecord(evA, 0);
    conv_off_kernel<<<gc, 64>>>(x, w_off, b_off, 2);
    cudaEventRecord(evB, 0);

    cudaStreamWaitEvent(s2, evA, 0);
    sample_kernel<<<gs, ts, 0, s2>>>(x, out, 0);
    cudaStreamWaitEvent(s2, evB, 0);
    sample_kernel<<<gs, ts, 0, s2>>>(x, out, 2);

    cudaEventRecord(fin, s2);
    cudaStreamWaitEvent(0, fin, 0);
}

// round 17
// speedup vs baseline: 1.0768x; 1.0545x over previous
#include <cuda_runtime.h>
#include <cstdint>

#define Hh 512
#define Ww 512
#define Cc 32
#define Bb 4
#define Ss (Hh*Ww)
#define NG 4               // conv channel groups
#define CPG (Cc/NG)        // 8 channels per group

// Partial per-pixel (off_x, off_y) per channel-group: 4 * 8MB = 32 MB scratch
__device__ float2 g_off_part[NG][Bb * Ss];

typedef unsigned long long ull;

__device__ __forceinline__ ull pack2(float a, float b) {
    ull r; asm("mov.b64 %0, {%1, %2};" : "=l"(r) : "f"(a), "f"(b)); return r;
}
__device__ __forceinline__ void unpack2(ull v, float& a, float& b) {
    asm("mov.b64 {%0, %1}, %2;" : "=f"(a), "=f"(b) : "l"(v));
}
__device__ __forceinline__ ull fma2(ull a, ull b, ull c) {
    ull d; asm("fma.rn.f32x2 %0, %1, %2, %3;" : "=l"(d) : "l"(a), "l"(b), "l"(c)); return d;
}

// ---------------------------------------------------------------------------
// Kernel 1: channel-split conv with 2-channel ILP interleave — R13-exact
// (measured 34.7us, DRAM 54.6% / fma 45.3% / issue 48.1%: at its traffic
// floor). Full grid (4096 blocks) — R15/R16 proved every split drops its
// achieved DRAM BW (4.3 -> 2.4-3.3 TB/s) and overlap never materializes.
// Warp strip = 128px x 4 rows, barrier-free, 12 independent row-loads in
// flight per step, packed f32x2 accumulation. grid.z = batch*NG.
// ---------------------------------------------------------------------------
__global__ __launch_bounds__(64) void conv_off_kernel(
    const float* __restrict__ x,
    const float* __restrict__ w_off,
    const float* __restrict__ b_off)
{
    __shared__ ull s_wk[CPG * 9];

    const int tid  = threadIdx.x;
    const int wid  = tid >> 5;
    const int lane = tid & 31;

    const int grp = blockIdx.z & (NG - 1);
    const int bz  = blockIdx.z >> 2;
    const int c0  = grp * CPG;

    for (int i = tid; i < CPG * 9; i += 64)
        s_wk[i] = pack2(__ldg(w_off + c0 * 9 + i),
                        __ldg(w_off + 288 + c0 * 9 + i));
    __syncthreads();

    const int X0   = blockIdx.x * 128;
    const int ytop = blockIdx.y * 8 + wid * 4;
    const int cb   = X0 + 4 * lane;
    const float* xb = x + (size_t)bz * Cc * Ss;

    const ull initp = (grp == 0) ? pack2(__ldg(b_off + 0), __ldg(b_off + 1))
                                 : pack2(0.0f, 0.0f);
    ull acc[4][4];
#pragma unroll
    for (int r = 0; r < 4; r++)
#pragma unroll
        for (int p = 0; p < 4; p++) acc[r][p] = initp;

    const bool has_left  = (cb > 0);
    const bool has_right = (cb + 4 < Ww);

#pragma unroll
    for (int c = 0; c < CPG; c += 2) {
        const float* xcA = xb + (size_t)(c0 + c) * Ss;
        const float* xcB = xcA + Ss;

        ull wkA[9], wkB[9];
#pragma unroll
        for (int k = 0; k < 9; k++) {
            wkA[k] = s_wk[c * 9 + k];
            wkB[k] = s_wk[(c + 1) * 9 + k];
        }

        float4 mA[6], mB[6];
        float  lA[6], rA[6], lB[6], rB[6];
#pragma unroll
        for (int j = 0; j < 6; j++) {
            int gy = ytop - 1 + j;
            mA[j] = make_float4(0.f, 0.f, 0.f, 0.f);
            mB[j] = make_float4(0.f, 0.f, 0.f, 0.f);
            lA[j] = rA[j] = lB[j] = rB[j] = 0.f;
            if ((unsigned)gy < (unsigned)Hh) {
                const float* rpA = xcA + gy * Ww + cb;
                const float* rpB = xcB + gy * Ww + cb;
                mA[j] = __ldg(reinterpret_cast<const float4*>(rpA));
                mB[j] = __ldg(reinterpret_cast<const float4*>(rpB));
                if (has_left)  { lA[j] = __ldg(rpA - 1); lB[j] = __ldg(rpB - 1); }
                if (has_right) { rA[j] = __ldg(rpA + 4); rB[j] = __ldg(rpB + 4); }
            }
        }

#pragma unroll
        for (int j = 0; j < 6; j++) {
            ull pvA[6], pvB[6];
            pvA[0] = pack2(lA[j], lA[j]);     pvB[0] = pack2(lB[j], lB[j]);
            pvA[1] = pack2(mA[j].x, mA[j].x); pvB[1] = pack2(mB[j].x, mB[j].x);
            pvA[2] = pack2(mA[j].y, mA[j].y); pvB[2] = pack2(mB[j].y, mB[j].y);
            pvA[3] = pack2(mA[j].z, mA[j].z); pvB[3] = pack2(mB[j].z, mB[j].z);
            pvA[4] = pack2(mA[j].w, mA[j].w); pvB[4] = pack2(mB[j].w, mB[j].w);
            pvA[5] = pack2(rA[j], rA[j]);     pvB[5] = pack2(rB[j], rB[j]);

#pragma unroll
            for (int ky = 0; ky < 3; ky++) {
                int r = j - ky;
                if (r >= 0 && r < 4) {
#pragma unroll
                    for (int p = 0; p < 4; p++) {
                        ull a = acc[r][p];
                        a = fma2(pvA[p],     wkA[ky * 3 + 0], a);
                        a = fma2(pvA[p + 1], wkA[ky * 3 + 1], a);
                        a = fma2(pvA[p + 2], wkA[ky * 3 + 2], a);
                        a = fma2(pvB[p],     wkB[ky * 3 + 0], a);
                        a = fma2(pvB[p + 1], wkB[ky * 3 + 1], a);
                        a = fma2(pvB[p + 2], wkB[ky * 3 + 2], a);
                        acc[r][p] = a;
                    }
                }
            }
        }
    }

#pragma unroll
    for (int r = 0; r < 4; r++) {
        int y = ytop + r;
        float2* op = g_off_part[grp] + (size_t)bz * Ss + (size_t)y * Ww + cb;
        float ox0, oy0, ox1, oy1, ox2, oy2, ox3, oy3;
        unpack2(acc[r][0], ox0, oy0);
        unpack2(acc[r][1], ox1, oy1);
        unpack2(acc[r][2], ox2, oy2);
        unpack2(acc[r][3], ox3, oy3);
        *reinterpret_cast<float4*>(op)     = make_float4(ox0, oy0, ox1, oy1);
        *reinterpret_cast<float4*>(op + 2) = make_float4(ox2, oy2, ox3, oy3);
    }
}

// ---------------------------------------------------------------------------
// Kernel 2: direct-gather bilinear sampler — R13-exact (proven 66.5us at its
// L1-wavefront floor; staging, pairing, splitting and widening all measured
// worse). Full grid, one thread per pixel. Sums the 4 conv partials, full
// clamp+validity (jnp semantics), coalesced channel loop + streaming stores.
// ---------------------------------------------------------------------------
__global__ __launch_bounds__(256) void sample_kernel(
    const float* __restrict__ x,
    float* __restrict__ out)
{
    const int px = blockIdx.x * 64 + threadIdx.x;
    const int py = blockIdx.y * 4 + threadIdx.y;
    const int b  = blockIdx.z;

    const size_t oidx = (size_t)b * Ss + (size_t)py * Ww + px;
    float2 p0 = __ldg(&g_off_part[0][oidx]);
    float2 p1 = __ldg(&g_off_part[1][oidx]);
    float2 p2 = __ldg(&g_off_part[2][oidx]);
    float2 p3 = __ldg(&g_off_part[3][oidx]);
    float offx = (p0.x + p1.x) + (p2.x + p3.x);
    float offy = (p0.y + p1.y) + (p2.y + p3.y);

    float ix = (float)px + offx;
    float iy = (float)py + offy;

    float x0f = floorf(ix);
    float y0f = floorf(iy);
    float wx1 = ix - x0f, wx0 = 1.0f - wx1;
    float wy1 = iy - y0f, wy0 = 1.0f - wy1;

    float fx0 = (x0f >= 0.0f && x0f <= 511.0f) ? 1.0f : 0.0f;
    float fx1 = (x0f >= -1.0f && x0f <= 510.0f) ? 1.0f : 0.0f;
    float fy0 = (y0f >= 0.0f && y0f <= 511.0f) ? 1.0f : 0.0f;
    float fy1 = (y0f >= -1.0f && y0f <= 510.0f) ? 1.0f : 0.0f;

    int ix0r = (int)x0f;
    int iy0r = (int)y0f;
    int xi0 = max(0, min(511, ix0r));
    int xi1 = max(0, min(511, ix0r + 1));
    int yi0 = max(0, min(511, iy0r));
    int yi1 = max(0, min(511, iy0r + 1));

    float w00 = wy0 * wx0 * (fy0 * fx0);
    float w01 = wy0 * wx1 * (fy0 * fx1);
    float w10 = wy1 * wx0 * (fy1 * fx0);
    float w11 = wy1 * wx1 * (fy1 * fx1);

    const int i00 = yi0 * Ww + xi0;
    const int i01 = yi0 * Ww + xi1;
    const int i10 = yi1 * Ww + xi0;
    const int i11 = yi1 * Ww + xi1;

    const float* xb = x + (size_t)b * Cc * Ss;
    size_t o = (size_t)b * Cc * Ss + (size_t)py * Ww + px;

#pragma unroll 4
    for (int c = 0; c < Cc; c++) {
        const float* p = xb + (size_t)c * Ss;
        float v = w00 * __ldg(p + i00)
                + w01 * __ldg(p + i01)
                + w10 * __ldg(p + i10)
                + w11 * __ldg(p + i11);
        __stcs(out + o + (size_t)c * Ss, v);
    }
}

extern "C" void kernel_launch(void* const* d_in, const int* in_sizes, int n_in,
                              void* d_out, int out_size)
{
    const float* x     = (const float*)d_in[0];  // (4, 32, 512, 512)
    const float* w_off = (const float*)d_in[1];  // (18, 32, 3, 3)
    const float* b_off = (const float*)d_in[2];  // (18,)
    float* out = (float*)d_out;                  // (4, 32, 512, 512)

    (void)in_sizes; (void)n_in; (void)out_size;

    dim3 g1(Ww / 128, Hh / 8, Bb * NG);   // (4, 64, 16) blocks x 64 thr
    conv_off_kernel<<<g1, 64>>>(x, w_off, b_off);

    dim3 g2(Ww / 64, Hh / 4, Bb);         // (8, 128, 4) blocks x (64,4) thr
    dim3 t2(64, 4);
    sample_kernel<<<g2, t2>>>(x, out);
}